// round 11
// baseline (speedup 1.0000x reference)
#include <cuda_runtime.h>
#include <math.h>
#include <stdint.h>

// ---------------------------------------------------------------------------
// B=4, S=4096, HID=2048, H=16, G=4, D=128, KV=512, M = B*S = 16384, K = 2048
// ---------------------------------------------------------------------------
#define M_ROWS 16384
#define KDIM   2048
#define HID    2048
#define KVDIM  512

// Scratch (__device__ globals: allocation-free rule)
__device__ __align__(128) float g_q[(size_t)M_ROWS * HID];
__device__ __align__(128) float g_k[(size_t)M_ROWS * KVDIM];
__device__ __align__(128) float g_v[(size_t)M_ROWS * KVDIM];
__device__ __align__(128) float g_attn[(size_t)M_ROWS * HID];
__device__ __align__(128) float g_xr[(size_t)M_ROWS * HID];
__device__ __align__(128) float g_wqt[(size_t)HID * KDIM];
__device__ __align__(128) float g_wkt[(size_t)KVDIM * KDIM];
__device__ __align__(128) float g_wvt[(size_t)KVDIM * KDIM];
__device__ __align__(128) float g_wot[(size_t)HID * KDIM];

// ---------------------------------------------------------------------------
// PTX helpers (base sm_103 ISA only — no 'a'-suffix features)
// ---------------------------------------------------------------------------
__device__ __forceinline__ uint32_t smem_u32(const void* p) {
    uint32_t a;
    asm("{ .reg .u64 t; cvta.to.shared.u64 t, %1; cvt.u32.u64 %0, t; }" : "=r"(a) : "l"(p));
    return a;
}
__device__ __forceinline__ unsigned f2tf32(float x) {
    unsigned r;
    asm("cvt.rna.tf32.f32 %0, %1;" : "=r"(r) : "f"(x));
    return r;
}
__device__ __forceinline__ void cp_async16(uint32_t saddr, const void* gmem) {
    asm volatile("cp.async.cg.shared.global [%0], [%1], 16;\n" :: "r"(saddr), "l"(gmem));
}
__device__ __forceinline__ void cp_commit() { asm volatile("cp.async.commit_group;\n"); }
template <int N>
__device__ __forceinline__ void cp_wait() { asm volatile("cp.async.wait_group %0;\n" :: "n"(N)); }

__device__ __forceinline__ void ldsm4(uint32_t r[4], uint32_t addr) {
    asm volatile("ldmatrix.sync.aligned.m8n8.x4.shared.b16 {%0,%1,%2,%3}, [%4];"
                 : "=r"(r[0]), "=r"(r[1]), "=r"(r[2]), "=r"(r[3]) : "r"(addr));
}
__device__ __forceinline__ void mma_tf32(float c[4],
                                         const uint32_t a[4], uint32_t b0, uint32_t b1) {
    asm volatile(
        "mma.sync.aligned.m16n8k8.row.col.f32.tf32.tf32.f32 "
        "{%0,%1,%2,%3}, {%4,%5,%6,%7}, {%8,%9}, {%0,%1,%2,%3};\n"
        : "+f"(c[0]), "+f"(c[1]), "+f"(c[2]), "+f"(c[3])
        : "r"(a[0]), "r"(a[1]), "r"(a[2]), "r"(a[3]), "r"(b0), "r"(b1));
}

// ---------------------------------------------------------------------------
// GEMM: C[M,N] = A[M,K] @ Bt[N,K]^T + bias     (A,Bt pre-rounded to tf32-rna)
// CTA tile 128(M) x 256(N), BK=32 floats. 512 threads = 16 warps (4x4 grid),
// warp tile 32x64. 3-stage cp.async ring, XOR-swizzled smem, ldmatrix loads.
// 4 warps per SMSP for latency hiding (vs 2 in the 256-thread version).
// ---------------------------------------------------------------------------
#define NSTAGE 3
#define KT_CNT 64                       // K / 32
#define STG_A  16384                    // 128 rows * 128 B
#define STG_B  32768                    // 256 rows * 128 B
#define SM_B_OFF (NSTAGE * STG_A)
#define SMEM_BYTES (NSTAGE * (STG_A + STG_B))   // 147456

__global__ void __launch_bounds__(512, 1)
gemm_tc(const float* __restrict__ A, const float* __restrict__ Bt,
        const float* __restrict__ bias, float* __restrict__ C, int N) {
    extern __shared__ char smem[];
    const uint32_t sb = smem_u32(smem);
    const int tid = threadIdx.x, warp = tid >> 5, lane = tid & 31;
    const int wm = warp >> 2, wn = warp & 3;       // 4x4 warp grid
    const int bm = blockIdx.y * 128;
    const int bn = blockIdx.x * 256;

    // ---- per-lane ldmatrix address bases (swizzle folded; bits disjoint) ----
    uint32_t aBase[2], aXk[2], bBase[4], bXk[4];
    {
        const int f = lane >> 3;
        // A: frag f -> rows ((f&1)*8 + l%8), k-chunk (f>>1)
        const int rinA = ((f & 1) << 3) | (lane & 7);
        const int cfA = f >> 1;
#pragma unroll
        for (int mi = 0; mi < 2; mi++) {
            const int row = wm * 32 + mi * 16 + rinA;
            const int rm = row & 7;
            aBase[mi] = (uint32_t)(row * 128 + ((cfA ^ (rm & 1)) << 4));
            aXk[mi]   = (uint32_t)((rm & 6) << 4);
        }
        // B: frag f -> n-rows ((f>>1)*8 + l%8), k-chunk (f&1)
        const int rinB = ((f >> 1) << 3) | (lane & 7);
        const int cfB = f & 1;
#pragma unroll
        for (int p = 0; p < 4; p++) {
            const int nrow = wn * 64 + p * 16 + rinB;
            const int rm = nrow & 7;
            bBase[p] = (uint32_t)(nrow * 128 + ((cfB ^ (rm & 1)) << 4));
            bXk[p]   = (uint32_t)((rm & 6) << 4);
        }
    }

    float acc[2][8][4];
#pragma unroll
    for (int i = 0; i < 2; i++)
#pragma unroll
        for (int j = 0; j < 8; j++)
#pragma unroll
            for (int c = 0; c < 4; c++) acc[i][j][c] = 0.f;

    // gmem->smem: 16B chunks, swizzled chunk = c ^ (row&7)
    auto load_stage = [&](int kt, int buf) {
        // A: 1024 chunks / 512 threads
#pragma unroll
        for (int i = 0; i < 2; i++) {
            const int idx = tid + i * 512;
            const int row = idx >> 3, c = idx & 7;
            const uint32_t sw = (uint32_t)(row * 128 + ((c ^ (row & 7)) << 4));
            cp_async16(sb + buf * STG_A + sw,
                       A + (size_t)(bm + row) * KDIM + kt * 32 + c * 4);
        }
        // B: 2048 chunks / 512 threads
#pragma unroll
        for (int i = 0; i < 4; i++) {
            const int idx = tid + i * 512;
            const int row = idx >> 3, c = idx & 7;
            const uint32_t sw = (uint32_t)(row * 128 + ((c ^ (row & 7)) << 4));
            cp_async16(sb + SM_B_OFF + buf * STG_B + sw,
                       Bt + (size_t)(bn + row) * KDIM + kt * 32 + c * 4);
        }
        cp_commit();
    };

#pragma unroll
    for (int s = 0; s < NSTAGE; s++) load_stage(s, s);

    for (int kt = 0; kt < KT_CNT; kt++) {
        if (kt < KT_CNT - 1) cp_wait<1>();
        else                 cp_wait<0>();
        __syncthreads();
        // buffer (kt+2)%3 == (kt-1)%3 was consumed at kt-1 and fenced by the sync
        if (kt >= 1 && kt + 2 < KT_CNT) load_stage(kt + 2, (kt + 2) % 3);

        const int buf = kt % 3;
        const uint32_t aS = sb + buf * STG_A;
        const uint32_t bS = sb + SM_B_OFF + buf * STG_B;
#pragma unroll
        for (int ks = 0; ks < 4; ks++) {
            uint32_t a[2][4];
#pragma unroll
            for (int mi = 0; mi < 2; mi++)
                ldsm4(a[mi], aS + (aBase[mi] | ((32u * ks) ^ aXk[mi])));
            uint32_t b[4][4];
#pragma unroll
            for (int p = 0; p < 4; p++)
                ldsm4(b[p], bS + (bBase[p] | ((32u * ks) ^ bXk[p])));
#pragma unroll
            for (int mi = 0; mi < 2; mi++)
#pragma unroll
                for (int p = 0; p < 4; p++) {
                    mma_tf32(acc[mi][2 * p],     a[mi], b[p][0], b[p][1]);
                    mma_tf32(acc[mi][2 * p + 1], a[mi], b[p][2], b[p][3]);
                }
        }
    }

    // epilogue: + bias, fp32 out
    const int g = lane >> 2, tig = lane & 3;
#pragma unroll
    for (int mi = 0; mi < 2; mi++) {
#pragma unroll
        for (int ni = 0; ni < 8; ni++) {
            const int row = bm + wm * 32 + mi * 16 + g;
            const int col = bn + wn * 64 + ni * 8 + tig * 2;
            const float bv0 = bias[col], bv1 = bias[col + 1];
            float2 o0 = {acc[mi][ni][0] + bv0, acc[mi][ni][1] + bv1};
            float2 o1 = {acc[mi][ni][2] + bv0, acc[mi][ni][3] + bv1};
            *(float2*)(C + (size_t)row * N + col)       = o0;
            *(float2*)(C + (size_t)(row + 8) * N + col) = o1;
        }
    }
}

// ---------------------------------------------------------------------------
// Weight transpose + tf32-rna rounding: Wt[n,k] = rna(W[k,n]); W is [K,N]
// ---------------------------------------------------------------------------
__global__ void __launch_bounds__(256)
transpose_round(const float* __restrict__ W, float* __restrict__ Wt, int K, int N) {
    __shared__ float t[32][33];
    const int k0 = blockIdx.x * 32, n0 = blockIdx.y * 32;
    const int tx = threadIdx.x & 31, ty = threadIdx.x >> 5;   // ty 0..7
#pragma unroll
    for (int i = 0; i < 32; i += 8)
        t[ty + i][tx] = W[(size_t)(k0 + ty + i) * N + n0 + tx];
    __syncthreads();
#pragma unroll
    for (int i = 0; i < 32; i += 8)
        Wt[(size_t)(n0 + ty + i) * K + k0 + tx] = __uint_as_float(f2tf32(t[tx][ty + i]));
}

// x -> rna-rounded copy (so raw bits fed to tf32 MMA == rna-rounded operand)
__global__ void __launch_bounds__(256)
round4(const float4* __restrict__ in, float4* __restrict__ out, int n4) {
    for (int i = blockIdx.x * 256 + threadIdx.x; i < n4; i += gridDim.x * 256) {
        float4 v = in[i];
        v.x = __uint_as_float(f2tf32(v.x));
        v.y = __uint_as_float(f2tf32(v.y));
        v.z = __uint_as_float(f2tf32(v.z));
        v.w = __uint_as_float(f2tf32(v.w));
        out[i] = v;
    }
}

// ---------------------------------------------------------------------------
// Attention over G=4 groups at same position; output rna-rounded (feeds the
// tf32 O-projection as the A operand).
// ---------------------------------------------------------------------------
__global__ void __launch_bounds__(256)
attn_kernel(const float* __restrict__ Q, const float* __restrict__ Kp,
            const float* __restrict__ Vp, float* __restrict__ Out) {
    const int m = blockIdx.x;
    __shared__ float ks[512], vs[512];
    const int tid = threadIdx.x;
    const float* kr = Kp + (size_t)m * KVDIM;
    const float* vr = Vp + (size_t)m * KVDIM;
    for (int i = tid; i < 512; i += 256) { ks[i] = kr[i]; vs[i] = vr[i]; }
    __syncthreads();

    const int warp = tid >> 5, lane = tid & 31;
    const float* qr   = Q   + (size_t)m * HID;
    float*       orow = Out + (size_t)m * HID;

#pragma unroll
    for (int hh = 0; hh < 2; ++hh) {
        const int h = warp * 2 + hh;
        float qv[4];
#pragma unroll
        for (int j = 0; j < 4; j++) qv[j] = qr[h * 128 + lane + 32 * j];
        float s[4];
#pragma unroll
        for (int gi = 0; gi < 4; ++gi) {
            float p = 0.f;
#pragma unroll
            for (int j = 0; j < 4; j++) p += qv[j] * ks[gi * 128 + lane + 32 * j];
#pragma unroll
            for (int off = 16; off > 0; off >>= 1)
                p += __shfl_xor_sync(0xffffffffu, p, off);
            s[gi] = p * 0.088388347648318447f;   // 1/sqrt(128)
        }
        const float mx = fmaxf(fmaxf(s[0], s[1]), fmaxf(s[2], s[3]));
        float e0 = __expf(s[0] - mx), e1 = __expf(s[1] - mx);
        float e2 = __expf(s[2] - mx), e3 = __expf(s[3] - mx);
        const float inv = 1.f / (e0 + e1 + e2 + e3);
        e0 *= inv; e1 *= inv; e2 *= inv; e3 *= inv;
#pragma unroll
        for (int j = 0; j < 4; j++) {
            const int d = lane + 32 * j;
            const float o = e0 * vs[d] + e1 * vs[128 + d] +
                            e2 * vs[256 + d] + e3 * vs[384 + d];
            orow[h * 128 + d] = __uint_as_float(f2tf32(o));
        }
    }
}

// ---------------------------------------------------------------------------
// Launch: hidden_states, Wq, bq, Wk, bk, Wv, bv, Wo, bo
// ---------------------------------------------------------------------------
extern "C" void kernel_launch(void* const* d_in, const int* in_sizes, int n_in,
                              void* d_out, int out_size) {
    const float* x  = (const float*)d_in[0];
    const float* Wq = (const float*)d_in[1];
    const float* bq = (const float*)d_in[2];
    const float* Wk = (const float*)d_in[3];
    const float* bk = (const float*)d_in[4];
    const float* Wv = (const float*)d_in[5];
    const float* bv = (const float*)d_in[6];
    const float* Wo = (const float*)d_in[7];
    const float* bo = (const float*)d_in[8];
    float* out = (float*)d_out;

    float *q, *k, *v, *attn, *xr, *wqt, *wkt, *wvt, *wot;
    cudaGetSymbolAddress((void**)&q,    g_q);
    cudaGetSymbolAddress((void**)&k,    g_k);
    cudaGetSymbolAddress((void**)&v,    g_v);
    cudaGetSymbolAddress((void**)&attn, g_attn);
    cudaGetSymbolAddress((void**)&xr,   g_xr);
    cudaGetSymbolAddress((void**)&wqt,  g_wqt);
    cudaGetSymbolAddress((void**)&wkt,  g_wkt);
    cudaGetSymbolAddress((void**)&wvt,  g_wvt);
    cudaGetSymbolAddress((void**)&wot,  g_wot);

    cudaFuncSetAttribute(gemm_tc, cudaFuncAttributeMaxDynamicSharedMemorySize, SMEM_BYTES);

    // Prep: transpose+round weights, round activations
    transpose_round<<<dim3(KDIM / 32, HID / 32),   256>>>(Wq, wqt, KDIM, HID);
    transpose_round<<<dim3(KDIM / 32, KVDIM / 32), 256>>>(Wk, wkt, KDIM, KVDIM);
    transpose_round<<<dim3(KDIM / 32, KVDIM / 32), 256>>>(Wv, wvt, KDIM, KVDIM);
    transpose_round<<<dim3(KDIM / 32, HID / 32),   256>>>(Wo, wot, KDIM, HID);
    round4<<<8192, 256>>>((const float4*)x, (float4*)xr, (M_ROWS * HID) / 4);

    // Projections (tf32 tensor cores, ldmatrix path)
    gemm_tc<<<dim3(HID / 256,   M_ROWS / 128), 512, SMEM_BYTES>>>(xr, wqt, bq, q, HID);
    gemm_tc<<<dim3(KVDIM / 256, M_ROWS / 128), 512, SMEM_BYTES>>>(xr, wkt, bk, k, KVDIM);
    gemm_tc<<<dim3(KVDIM / 256, M_ROWS / 128), 512, SMEM_BYTES>>>(xr, wvt, bv, v, KVDIM);

    // Attention (writes rna-rounded A operand for O-projection)
    attn_kernel<<<M_ROWS, 256>>>(q, k, v, attn);

    // Output projection
    gemm_tc<<<dim3(HID / 256, M_ROWS / 128), 512, SMEM_BYTES>>>(attn, wot, bo, out, HID);
}

// round 12
// speedup vs baseline: 1.6045x; 1.6045x over previous
#include <cuda_runtime.h>
#include <math.h>
#include <stdint.h>

// ---------------------------------------------------------------------------
// B=4, S=4096, HID=2048, H=16, G=4, D=128, KV=512, M = B*S = 16384, K = 2048
// ---------------------------------------------------------------------------
#define M_ROWS 16384
#define KDIM   2048
#define HID    2048
#define KVDIM  512

// Scratch (__device__ globals: allocation-free rule)
__device__ __align__(128) float g_q[(size_t)M_ROWS * HID];
__device__ __align__(128) float g_k[(size_t)M_ROWS * KVDIM];
__device__ __align__(128) float g_v[(size_t)M_ROWS * KVDIM];
__device__ __align__(128) float g_attn[(size_t)M_ROWS * HID];
__device__ __align__(128) float g_xr[(size_t)M_ROWS * HID];
__device__ __align__(128) float g_wqt[(size_t)HID * KDIM];
__device__ __align__(128) float g_wkt[(size_t)KVDIM * KDIM];
__device__ __align__(128) float g_wvt[(size_t)KVDIM * KDIM];
__device__ __align__(128) float g_wot[(size_t)HID * KDIM];

// ---------------------------------------------------------------------------
// PTX helpers (base sm_103 ISA only — no 'a'-suffix features)
// ---------------------------------------------------------------------------
__device__ __forceinline__ uint32_t smem_u32(const void* p) {
    uint32_t a;
    asm("{ .reg .u64 t; cvta.to.shared.u64 t, %1; cvt.u32.u64 %0, t; }" : "=r"(a) : "l"(p));
    return a;
}
__device__ __forceinline__ unsigned f2tf32(float x) {
    unsigned r;
    asm("cvt.rna.tf32.f32 %0, %1;" : "=r"(r) : "f"(x));
    return r;
}
__device__ __forceinline__ void cp_async16(uint32_t saddr, const void* gmem) {
    asm volatile("cp.async.cg.shared.global [%0], [%1], 16;\n" :: "r"(saddr), "l"(gmem));
}
__device__ __forceinline__ void cp_commit() { asm volatile("cp.async.commit_group;\n"); }
template <int N>
__device__ __forceinline__ void cp_wait() { asm volatile("cp.async.wait_group %0;\n" :: "n"(N)); }

__device__ __forceinline__ void ldsm4(uint32_t r[4], uint32_t addr) {
    asm volatile("ldmatrix.sync.aligned.m8n8.x4.shared.b16 {%0,%1,%2,%3}, [%4];"
                 : "=r"(r[0]), "=r"(r[1]), "=r"(r[2]), "=r"(r[3]) : "r"(addr));
}
__device__ __forceinline__ void mma_tf32(float c[4],
                                         const uint32_t a[4], uint32_t b0, uint32_t b1) {
    asm volatile(
        "mma.sync.aligned.m16n8k8.row.col.f32.tf32.tf32.f32 "
        "{%0,%1,%2,%3}, {%4,%5,%6,%7}, {%8,%9}, {%0,%1,%2,%3};\n"
        : "+f"(c[0]), "+f"(c[1]), "+f"(c[2]), "+f"(c[3])
        : "r"(a[0]), "r"(a[1]), "r"(a[2]), "r"(a[3]), "r"(b0), "r"(b1));
}

// ---------------------------------------------------------------------------
// GEMM: C[M,N] = A[M,K] @ Bt[N,K]^T + bias     (A,Bt pre-rounded to tf32-rna)
// CTA tile 256(M) x 128(N), BK=32 floats. 256 threads = 8 warps (4x2 grid),
// warp tile 64x64 => 128 B crossbar traffic per MMA (vs 192 B at 32x64).
// 4-stage cp.async ring, XOR-swizzled smem, ldmatrix fragment loads.
// ---------------------------------------------------------------------------
#define NSTAGE 4
#define KT_CNT 64                       // K / 32
#define STG_A  32768                    // 256 rows * 128 B
#define STG_B  16384                    // 128 rows * 128 B
#define SM_B_OFF (NSTAGE * STG_A)
#define SMEM_BYTES (NSTAGE * (STG_A + STG_B))   // 196608

__global__ void __launch_bounds__(256, 1)
gemm_tc(const float* __restrict__ A, const float* __restrict__ Bt,
        const float* __restrict__ bias, float* __restrict__ C, int N) {
    extern __shared__ char smem[];
    const uint32_t sb = smem_u32(smem);
    const int tid = threadIdx.x, warp = tid >> 5, lane = tid & 31;
    const int wm = warp >> 1, wn = warp & 1;       // 4(m) x 2(n) warp grid
    const int bm = blockIdx.y * 256;
    const int bn = blockIdx.x * 128;

    // ---- per-lane ldmatrix address bases (swizzle folded; bits disjoint) ----
    uint32_t aBase[4], aXk, bBase[4], bXk[4];
    {
        const int f = lane >> 3;
        // A: frag f -> rows ((f&1)*8 + l%8), k-chunk (f>>1)
        const int rinA = ((f & 1) << 3) | (lane & 7);
        const int cfA = f >> 1;
        const int rmA = rinA & 7;                   // == lane&7 for all mi
        aXk = (uint32_t)((rmA & 6) << 4);
#pragma unroll
        for (int mi = 0; mi < 4; mi++) {
            const int row = wm * 64 + mi * 16 + rinA;
            aBase[mi] = (uint32_t)(row * 128 + ((cfA ^ (rmA & 1)) << 4));
        }
        // B: frag f -> n-rows ((f>>1)*8 + l%8), k-chunk (f&1)
        const int rinB = ((f >> 1) << 3) | (lane & 7);
        const int cfB = f & 1;
#pragma unroll
        for (int p = 0; p < 4; p++) {
            const int nrow = wn * 64 + p * 16 + rinB;
            const int rm = nrow & 7;
            bBase[p] = (uint32_t)(nrow * 128 + ((cfB ^ (rm & 1)) << 4));
            bXk[p]   = (uint32_t)((rm & 6) << 4);
        }
    }

    float acc[4][8][4];
#pragma unroll
    for (int i = 0; i < 4; i++)
#pragma unroll
        for (int j = 0; j < 8; j++)
#pragma unroll
            for (int c = 0; c < 4; c++) acc[i][j][c] = 0.f;

    // gmem->smem: 16B chunks, swizzled chunk = c ^ (row&7)
    auto load_stage = [&](int kt, int buf) {
        // A: 2048 chunks / 256 threads
#pragma unroll
        for (int i = 0; i < 8; i++) {
            const int idx = tid + i * 256;
            const int row = idx >> 3, c = idx & 7;
            const uint32_t sw = (uint32_t)(row * 128 + ((c ^ (row & 7)) << 4));
            cp_async16(sb + buf * STG_A + sw,
                       A + (size_t)(bm + row) * KDIM + kt * 32 + c * 4);
        }
        // B: 1024 chunks / 256 threads
#pragma unroll
        for (int i = 0; i < 4; i++) {
            const int idx = tid + i * 256;
            const int row = idx >> 3, c = idx & 7;
            const uint32_t sw = (uint32_t)(row * 128 + ((c ^ (row & 7)) << 4));
            cp_async16(sb + SM_B_OFF + buf * STG_B + sw,
                       Bt + (size_t)(bn + row) * KDIM + kt * 32 + c * 4);
        }
        cp_commit();
    };

#pragma unroll
    for (int s = 0; s < NSTAGE; s++) load_stage(s, s);

    for (int kt = 0; kt < KT_CNT; kt++) {
        if (kt < KT_CNT - 2)       cp_wait<2>();
        else if (kt == KT_CNT - 2) cp_wait<1>();
        else                       cp_wait<0>();
        __syncthreads();
        if (kt >= 1 && kt + 3 < KT_CNT) load_stage(kt + 3, (kt + 3) & 3);

        const int buf = kt & 3;
        const uint32_t aS = sb + buf * STG_A;
        const uint32_t bS = sb + SM_B_OFF + buf * STG_B;
#pragma unroll
        for (int ks = 0; ks < 4; ks++) {
            uint32_t a[4][4];
#pragma unroll
            for (int mi = 0; mi < 4; mi++)
                ldsm4(a[mi], aS + (aBase[mi] | ((32u * ks) ^ aXk)));
            uint32_t b[4][4];
#pragma unroll
            for (int p = 0; p < 4; p++)
                ldsm4(b[p], bS + (bBase[p] | ((32u * ks) ^ bXk[p])));
#pragma unroll
            for (int mi = 0; mi < 4; mi++)
#pragma unroll
                for (int p = 0; p < 4; p++) {
                    mma_tf32(acc[mi][2 * p],     a[mi], b[p][0], b[p][1]);
                    mma_tf32(acc[mi][2 * p + 1], a[mi], b[p][2], b[p][3]);
                }
        }
    }

    // epilogue: + bias, fp32 out
    const int g = lane >> 2, tig = lane & 3;
#pragma unroll
    for (int mi = 0; mi < 4; mi++) {
#pragma unroll
        for (int ni = 0; ni < 8; ni++) {
            const int row = bm + wm * 64 + mi * 16 + g;
            const int col = bn + wn * 64 + ni * 8 + tig * 2;
            const float bv0 = bias[col], bv1 = bias[col + 1];
            float2 o0 = {acc[mi][ni][0] + bv0, acc[mi][ni][1] + bv1};
            float2 o1 = {acc[mi][ni][2] + bv0, acc[mi][ni][3] + bv1};
            *(float2*)(C + (size_t)row * N + col)       = o0;
            *(float2*)(C + (size_t)(row + 8) * N + col) = o1;
        }
    }
}

// ---------------------------------------------------------------------------
// Weight transpose + tf32-rna rounding: Wt[n,k] = rna(W[k,n]); W is [K,N]
// ---------------------------------------------------------------------------
__global__ void __launch_bounds__(256)
transpose_round(const float* __restrict__ W, float* __restrict__ Wt, int K, int N) {
    __shared__ float t[32][33];
    const int k0 = blockIdx.x * 32, n0 = blockIdx.y * 32;
    const int tx = threadIdx.x & 31, ty = threadIdx.x >> 5;   // ty 0..7
#pragma unroll
    for (int i = 0; i < 32; i += 8)
        t[ty + i][tx] = W[(size_t)(k0 + ty + i) * N + n0 + tx];
    __syncthreads();
#pragma unroll
    for (int i = 0; i < 32; i += 8)
        Wt[(size_t)(n0 + ty + i) * K + k0 + tx] = __uint_as_float(f2tf32(t[tx][ty + i]));
}

// x -> rna-rounded copy (so raw bits fed to tf32 MMA == rna-rounded operand)
__global__ void __launch_bounds__(256)
round4(const float4* __restrict__ in, float4* __restrict__ out, int n4) {
    for (int i = blockIdx.x * 256 + threadIdx.x; i < n4; i += gridDim.x * 256) {
        float4 v = in[i];
        v.x = __uint_as_float(f2tf32(v.x));
        v.y = __uint_as_float(f2tf32(v.y));
        v.z = __uint_as_float(f2tf32(v.z));
        v.w = __uint_as_float(f2tf32(v.w));
        out[i] = v;
    }
}

// ---------------------------------------------------------------------------
// Attention over G=4 groups at same position; output rna-rounded (feeds the
// tf32 O-projection as the A operand).
// ---------------------------------------------------------------------------
__global__ void __launch_bounds__(256)
attn_kernel(const float* __restrict__ Q, const float* __restrict__ Kp,
            const float* __restrict__ Vp, float* __restrict__ Out) {
    const int m = blockIdx.x;
    __shared__ float ks[512], vs[512];
    const int tid = threadIdx.x;
    const float* kr = Kp + (size_t)m * KVDIM;
    const float* vr = Vp + (size_t)m * KVDIM;
    for (int i = tid; i < 512; i += 256) { ks[i] = kr[i]; vs[i] = vr[i]; }
    __syncthreads();

    const int warp = tid >> 5, lane = tid & 31;
    const float* qr   = Q   + (size_t)m * HID;
    float*       orow = Out + (size_t)m * HID;

#pragma unroll
    for (int hh = 0; hh < 2; ++hh) {
        const int h = warp * 2 + hh;
        float qv[4];
#pragma unroll
        for (int j = 0; j < 4; j++) qv[j] = qr[h * 128 + lane + 32 * j];
        float s[4];
#pragma unroll
        for (int gi = 0; gi < 4; ++gi) {
            float p = 0.f;
#pragma unroll
            for (int j = 0; j < 4; j++) p += qv[j] * ks[gi * 128 + lane + 32 * j];
#pragma unroll
            for (int off = 16; off > 0; off >>= 1)
                p += __shfl_xor_sync(0xffffffffu, p, off);
            s[gi] = p * 0.088388347648318447f;   // 1/sqrt(128)
        }
        const float mx = fmaxf(fmaxf(s[0], s[1]), fmaxf(s[2], s[3]));
        float e0 = __expf(s[0] - mx), e1 = __expf(s[1] - mx);
        float e2 = __expf(s[2] - mx), e3 = __expf(s[3] - mx);
        const float inv = 1.f / (e0 + e1 + e2 + e3);
        e0 *= inv; e1 *= inv; e2 *= inv; e3 *= inv;
#pragma unroll
        for (int j = 0; j < 4; j++) {
            const int d = lane + 32 * j;
            const float o = e0 * vs[d] + e1 * vs[128 + d] +
                            e2 * vs[256 + d] + e3 * vs[384 + d];
            orow[h * 128 + d] = __uint_as_float(f2tf32(o));
        }
    }
}

// ---------------------------------------------------------------------------
// Launch: hidden_states, Wq, bq, Wk, bk, Wv, bv, Wo, bo
// ---------------------------------------------------------------------------
extern "C" void kernel_launch(void* const* d_in, const int* in_sizes, int n_in,
                              void* d_out, int out_size) {
    const float* x  = (const float*)d_in[0];
    const float* Wq = (const float*)d_in[1];
    const float* bq = (const float*)d_in[2];
    const float* Wk = (const float*)d_in[3];
    const float* bk = (const float*)d_in[4];
    const float* Wv = (const float*)d_in[5];
    const float* bv = (const float*)d_in[6];
    const float* Wo = (const float*)d_in[7];
    const float* bo = (const float*)d_in[8];
    float* out = (float*)d_out;

    float *q, *k, *v, *attn, *xr, *wqt, *wkt, *wvt, *wot;
    cudaGetSymbolAddress((void**)&q,    g_q);
    cudaGetSymbolAddress((void**)&k,    g_k);
    cudaGetSymbolAddress((void**)&v,    g_v);
    cudaGetSymbolAddress((void**)&attn, g_attn);
    cudaGetSymbolAddress((void**)&xr,   g_xr);
    cudaGetSymbolAddress((void**)&wqt,  g_wqt);
    cudaGetSymbolAddress((void**)&wkt,  g_wkt);
    cudaGetSymbolAddress((void**)&wvt,  g_wvt);
    cudaGetSymbolAddress((void**)&wot,  g_wot);

    cudaFuncSetAttribute(gemm_tc, cudaFuncAttributeMaxDynamicSharedMemorySize, SMEM_BYTES);

    // Prep: transpose+round weights, round activations
    transpose_round<<<dim3(KDIM / 32, HID / 32),   256>>>(Wq, wqt, KDIM, HID);
    transpose_round<<<dim3(KDIM / 32, KVDIM / 32), 256>>>(Wk, wkt, KDIM, KVDIM);
    transpose_round<<<dim3(KDIM / 32, KVDIM / 32), 256>>>(Wv, wvt, KDIM, KVDIM);
    transpose_round<<<dim3(KDIM / 32, HID / 32),   256>>>(Wo, wot, KDIM, HID);
    round4<<<8192, 256>>>((const float4*)x, (float4*)xr, (M_ROWS * HID) / 4);

    // Projections (tf32 tensor cores, ldmatrix path)
    gemm_tc<<<dim3(HID / 128,   M_ROWS / 256), 256, SMEM_BYTES>>>(xr, wqt, bq, q, HID);
    gemm_tc<<<dim3(KVDIM / 128, M_ROWS / 256), 256, SMEM_BYTES>>>(xr, wkt, bk, k, KVDIM);
    gemm_tc<<<dim3(KVDIM / 128, M_ROWS / 256), 256, SMEM_BYTES>>>(xr, wvt, bv, v, KVDIM);

    // Attention (writes rna-rounded A operand for O-projection)
    attn_kernel<<<M_ROWS, 256>>>(q, k, v, attn);

    // Output projection
    gemm_tc<<<dim3(HID / 128, M_ROWS / 256), 256, SMEM_BYTES>>>(attn, wot, bo, out, HID);
}

// round 13
// speedup vs baseline: 2.9395x; 1.8320x over previous
#include <cuda_runtime.h>
#include <cuda_fp16.h>
#include <math.h>
#include <stdint.h>

// ---------------------------------------------------------------------------
// B=4, S=4096, HID=2048, H=16, G=4, D=128, KV=512, M = B*S = 16384, K = 2048
// ---------------------------------------------------------------------------
#define M_ROWS 16384
#define KDIM   2048
#define HID    2048
#define KVDIM  512

// Scratch (__device__ globals: allocation-free rule)
__device__ __align__(128) float  g_q[(size_t)M_ROWS * HID];
__device__ __align__(128) float  g_k[(size_t)M_ROWS * KVDIM];
__device__ __align__(128) float  g_v[(size_t)M_ROWS * KVDIM];
__device__ __align__(128) __half g_attnh[(size_t)M_ROWS * HID];
__device__ __align__(128) __half g_xh[(size_t)M_ROWS * HID];
__device__ __align__(128) __half g_wqt[(size_t)HID * KDIM];
__device__ __align__(128) __half g_wkt[(size_t)KVDIM * KDIM];
__device__ __align__(128) __half g_wvt[(size_t)KVDIM * KDIM];
__device__ __align__(128) __half g_wot[(size_t)HID * KDIM];

// ---------------------------------------------------------------------------
// PTX helpers (base sm_103 ISA only)
// ---------------------------------------------------------------------------
__device__ __forceinline__ uint32_t smem_u32(const void* p) {
    uint32_t a;
    asm("{ .reg .u64 t; cvta.to.shared.u64 t, %1; cvt.u32.u64 %0, t; }" : "=r"(a) : "l"(p));
    return a;
}
__device__ __forceinline__ void cp_async16(uint32_t saddr, const void* gmem) {
    asm volatile("cp.async.cg.shared.global [%0], [%1], 16;\n" :: "r"(saddr), "l"(gmem));
}
__device__ __forceinline__ void cp_commit() { asm volatile("cp.async.commit_group;\n"); }
template <int N>
__device__ __forceinline__ void cp_wait() { asm volatile("cp.async.wait_group %0;\n" :: "n"(N)); }

__device__ __forceinline__ void ldsm4(uint32_t r[4], uint32_t addr) {
    asm volatile("ldmatrix.sync.aligned.m8n8.x4.shared.b16 {%0,%1,%2,%3}, [%4];"
                 : "=r"(r[0]), "=r"(r[1]), "=r"(r[2]), "=r"(r[3]) : "r"(addr));
}
// fp16 MMA, fp32 accumulate: m16n8k16
__device__ __forceinline__ void mma_f16(float c[4],
                                        const uint32_t a[4], uint32_t b0, uint32_t b1) {
    asm volatile(
        "mma.sync.aligned.m16n8k16.row.col.f32.f16.f16.f32 "
        "{%0,%1,%2,%3}, {%4,%5,%6,%7}, {%8,%9}, {%0,%1,%2,%3};\n"
        : "+f"(c[0]), "+f"(c[1]), "+f"(c[2]), "+f"(c[3])
        : "r"(a[0]), "r"(a[1]), "r"(a[2]), "r"(a[3]), "r"(b0), "r"(b1));
}

// ---------------------------------------------------------------------------
// GEMM: C[M,N] = A[M,K] @ Bt[N,K]^T + bias   (A,Bt fp16; C fp32)
// CTA tile 256(M) x 128(N), BK=64 halves (128 B/row). 256 threads = 8 warps
// (4x2), warp tile 64x64. Per k16 step: 8 ldsm4 -> 32 m16n8k16 MMAs.
// 4-stage cp.async ring, XOR-swizzled smem (identical geometry to tf32 ver).
// ---------------------------------------------------------------------------
#define NSTAGE 4
#define KT_CNT 32                       // K / 64
#define STG_A  32768                    // 256 rows * 128 B
#define STG_B  16384                    // 128 rows * 128 B
#define SM_B_OFF (NSTAGE * STG_A)
#define SMEM_BYTES (NSTAGE * (STG_A + STG_B))   // 196608

__global__ void __launch_bounds__(256, 1)
gemm_tc(const __half* __restrict__ A, const __half* __restrict__ Bt,
        const float* __restrict__ bias, float* __restrict__ C, int N) {
    extern __shared__ char smem[];
    const uint32_t sb = smem_u32(smem);
    const int tid = threadIdx.x, warp = tid >> 5, lane = tid & 31;
    const int wm = warp >> 1, wn = warp & 1;       // 4(m) x 2(n) warp grid
    const int bm = blockIdx.y * 256;
    const int bn = blockIdx.x * 128;

    // ---- per-lane ldmatrix address bases (swizzle folded; bits disjoint) ----
    uint32_t aBase[4], aXk, bBase[4], bXk[4];
    {
        const int f = lane >> 3;
        // A: frag f -> m-rows ((f&1)*8 + l%8), k-chunk (f>>1)  [chunk = 16B = k8]
        const int rinA = ((f & 1) << 3) | (lane & 7);
        const int cfA = f >> 1;
        const int rmA = rinA & 7;
        aXk = (uint32_t)((rmA & 6) << 4);
#pragma unroll
        for (int mi = 0; mi < 4; mi++) {
            const int row = wm * 64 + mi * 16 + rinA;
            aBase[mi] = (uint32_t)(row * 128 + ((cfA ^ (rmA & 1)) << 4));
        }
        // B: frag f -> n-rows ((f>>1)*8 + l%8), k-chunk (f&1)
        const int rinB = ((f >> 1) << 3) | (lane & 7);
        const int cfB = f & 1;
#pragma unroll
        for (int p = 0; p < 4; p++) {
            const int nrow = wn * 64 + p * 16 + rinB;
            const int rm = nrow & 7;
            bBase[p] = (uint32_t)(nrow * 128 + ((cfB ^ (rm & 1)) << 4));
            bXk[p]   = (uint32_t)((rm & 6) << 4);
        }
    }

    float acc[4][8][4];
#pragma unroll
    for (int i = 0; i < 4; i++)
#pragma unroll
        for (int j = 0; j < 8; j++)
#pragma unroll
            for (int c = 0; c < 4; c++) acc[i][j][c] = 0.f;

    // gmem->smem: 16B chunks (=8 halves), swizzled chunk = c ^ (row&7)
    auto load_stage = [&](int kt, int buf) {
        // A: 256 rows x 8 chunks = 2048 chunks / 256 threads
#pragma unroll
        for (int i = 0; i < 8; i++) {
            const int idx = tid + i * 256;
            const int row = idx >> 3, c = idx & 7;
            const uint32_t sw = (uint32_t)(row * 128 + ((c ^ (row & 7)) << 4));
            cp_async16(sb + buf * STG_A + sw,
                       A + (size_t)(bm + row) * KDIM + kt * 64 + c * 8);
        }
        // B: 128 rows x 8 chunks = 1024 chunks / 256 threads
#pragma unroll
        for (int i = 0; i < 4; i++) {
            const int idx = tid + i * 256;
            const int row = idx >> 3, c = idx & 7;
            const uint32_t sw = (uint32_t)(row * 128 + ((c ^ (row & 7)) << 4));
            cp_async16(sb + SM_B_OFF + buf * STG_B + sw,
                       Bt + (size_t)(bn + row) * KDIM + kt * 64 + c * 8);
        }
        cp_commit();
    };

#pragma unroll
    for (int s = 0; s < NSTAGE; s++) load_stage(s, s);

    for (int kt = 0; kt < KT_CNT; kt++) {
        if (kt < KT_CNT - 2)       cp_wait<2>();
        else if (kt == KT_CNT - 2) cp_wait<1>();
        else                       cp_wait<0>();
        __syncthreads();
        if (kt >= 1 && kt + 3 < KT_CNT) load_stage(kt + 3, (kt + 3) & 3);

        const int buf = kt & 3;
        const uint32_t aS = sb + buf * STG_A;
        const uint32_t bS = sb + SM_B_OFF + buf * STG_B;
        // 4 k16 steps cover k64; chunk stride per step = 32 B (2 chunks)
#pragma unroll
        for (int ks = 0; ks < 4; ks++) {
            uint32_t a[4][4];
#pragma unroll
            for (int mi = 0; mi < 4; mi++)
                ldsm4(a[mi], aS + (aBase[mi] | ((32u * ks) ^ aXk)));
            uint32_t b[4][4];
#pragma unroll
            for (int p = 0; p < 4; p++)
                ldsm4(b[p], bS + (bBase[p] | ((32u * ks) ^ bXk[p])));
#pragma unroll
            for (int mi = 0; mi < 4; mi++)
#pragma unroll
                for (int p = 0; p < 4; p++) {
                    mma_f16(acc[mi][2 * p],     a[mi], b[p][0], b[p][1]);
                    mma_f16(acc[mi][2 * p + 1], a[mi], b[p][2], b[p][3]);
                }
        }
    }

    // epilogue: + bias, fp32 out
    const int g = lane >> 2, tig = lane & 3;
#pragma unroll
    for (int mi = 0; mi < 4; mi++) {
#pragma unroll
        for (int ni = 0; ni < 8; ni++) {
            const int row = bm + wm * 64 + mi * 16 + g;
            const int col = bn + wn * 64 + ni * 8 + tig * 2;
            const float bv0 = bias[col], bv1 = bias[col + 1];
            float2 o0 = {acc[mi][ni][0] + bv0, acc[mi][ni][1] + bv1};
            float2 o1 = {acc[mi][ni][2] + bv0, acc[mi][ni][3] + bv1};
            *(float2*)(C + (size_t)row * N + col)       = o0;
            *(float2*)(C + (size_t)(row + 8) * N + col) = o1;
        }
    }
}

// ---------------------------------------------------------------------------
// Weight transpose + fp16 conversion: Wt[n,k] = half(W[k,n]); W is [K,N] fp32
// ---------------------------------------------------------------------------
__global__ void __launch_bounds__(256)
transpose_h(const float* __restrict__ W, __half* __restrict__ Wt, int K, int N) {
    __shared__ float t[32][33];
    const int k0 = blockIdx.x * 32, n0 = blockIdx.y * 32;
    const int tx = threadIdx.x & 31, ty = threadIdx.x >> 5;   // ty 0..7
#pragma unroll
    for (int i = 0; i < 32; i += 8)
        t[ty + i][tx] = W[(size_t)(k0 + ty + i) * N + n0 + tx];
    __syncthreads();
#pragma unroll
    for (int i = 0; i < 32; i += 8)
        Wt[(size_t)(n0 + ty + i) * K + k0 + tx] = __float2half_rn(t[tx][ty + i]);
}

// fp32 -> fp16 elementwise (for activations feeding GEMM A operands)
__global__ void __launch_bounds__(256)
f2h4(const float4* __restrict__ in, __half2* __restrict__ out, int n4) {
    for (int i = blockIdx.x * 256 + threadIdx.x; i < n4; i += gridDim.x * 256) {
        float4 v = in[i];
        out[2 * i]     = __floats2half2_rn(v.x, v.y);
        out[2 * i + 1] = __floats2half2_rn(v.z, v.w);
    }
}

// ---------------------------------------------------------------------------
// Attention over G=4 groups at same position; writes fp16 (A operand of the
// O-projection GEMM). q/k/v inputs are fp32 GEMM outputs.
// ---------------------------------------------------------------------------
__global__ void __launch_bounds__(256)
attn_kernel(const float* __restrict__ Q, const float* __restrict__ Kp,
            const float* __restrict__ Vp, __half* __restrict__ Out) {
    const int m = blockIdx.x;
    __shared__ float ks[512], vs[512];
    const int tid = threadIdx.x;
    const float* kr = Kp + (size_t)m * KVDIM;
    const float* vr = Vp + (size_t)m * KVDIM;
    for (int i = tid; i < 512; i += 256) { ks[i] = kr[i]; vs[i] = vr[i]; }
    __syncthreads();

    const int warp = tid >> 5, lane = tid & 31;
    const float* qr   = Q   + (size_t)m * HID;
    __half*      orow = Out + (size_t)m * HID;

#pragma unroll
    for (int hh = 0; hh < 2; ++hh) {
        const int h = warp * 2 + hh;
        float qv[4];
#pragma unroll
        for (int j = 0; j < 4; j++) qv[j] = qr[h * 128 + lane + 32 * j];
        float s[4];
#pragma unroll
        for (int gi = 0; gi < 4; ++gi) {
            float p = 0.f;
#pragma unroll
            for (int j = 0; j < 4; j++) p += qv[j] * ks[gi * 128 + lane + 32 * j];
#pragma unroll
            for (int off = 16; off > 0; off >>= 1)
                p += __shfl_xor_sync(0xffffffffu, p, off);
            s[gi] = p * 0.088388347648318447f;   // 1/sqrt(128)
        }
        const float mx = fmaxf(fmaxf(s[0], s[1]), fmaxf(s[2], s[3]));
        float e0 = __expf(s[0] - mx), e1 = __expf(s[1] - mx);
        float e2 = __expf(s[2] - mx), e3 = __expf(s[3] - mx);
        const float inv = 1.f / (e0 + e1 + e2 + e3);
        e0 *= inv; e1 *= inv; e2 *= inv; e3 *= inv;
#pragma unroll
        for (int j = 0; j < 4; j++) {
            const int d = lane + 32 * j;
            const float o = e0 * vs[d] + e1 * vs[128 + d] +
                            e2 * vs[256 + d] + e3 * vs[384 + d];
            orow[h * 128 + d] = __float2half_rn(o);
        }
    }
}

// ---------------------------------------------------------------------------
// Launch: hidden_states, Wq, bq, Wk, bk, Wv, bv, Wo, bo
// ---------------------------------------------------------------------------
extern "C" void kernel_launch(void* const* d_in, const int* in_sizes, int n_in,
                              void* d_out, int out_size) {
    const float* x  = (const float*)d_in[0];
    const float* Wq = (const float*)d_in[1];
    const float* bq = (const float*)d_in[2];
    const float* Wk = (const float*)d_in[3];
    const float* bk = (const float*)d_in[4];
    const float* Wv = (const float*)d_in[5];
    const float* bv = (const float*)d_in[6];
    const float* Wo = (const float*)d_in[7];
    const float* bo = (const float*)d_in[8];
    float* out = (float*)d_out;

    float  *q, *k, *v;
    __half *attnh, *xh, *wqt, *wkt, *wvt, *wot;
    cudaGetSymbolAddress((void**)&q,     g_q);
    cudaGetSymbolAddress((void**)&k,     g_k);
    cudaGetSymbolAddress((void**)&v,     g_v);
    cudaGetSymbolAddress((void**)&attnh, g_attnh);
    cudaGetSymbolAddress((void**)&xh,    g_xh);
    cudaGetSymbolAddress((void**)&wqt,   g_wqt);
    cudaGetSymbolAddress((void**)&wkt,   g_wkt);
    cudaGetSymbolAddress((void**)&wvt,   g_wvt);
    cudaGetSymbolAddress((void**)&wot,   g_wot);

    cudaFuncSetAttribute(gemm_tc, cudaFuncAttributeMaxDynamicSharedMemorySize, SMEM_BYTES);

    // Prep: transpose+convert weights, convert activations
    transpose_h<<<dim3(KDIM / 32, HID / 32),   256>>>(Wq, wqt, KDIM, HID);
    transpose_h<<<dim3(KDIM / 32, KVDIM / 32), 256>>>(Wk, wkt, KDIM, KVDIM);
    transpose_h<<<dim3(KDIM / 32, KVDIM / 32), 256>>>(Wv, wvt, KDIM, KVDIM);
    transpose_h<<<dim3(KDIM / 32, HID / 32),   256>>>(Wo, wot, KDIM, HID);
    f2h4<<<8192, 256>>>((const float4*)x, (__half2*)xh, (M_ROWS * HID) / 4);

    // Projections (fp16 tensor cores, m16n8k16, fp32 accumulate)
    gemm_tc<<<dim3(HID / 128,   M_ROWS / 256), 256, SMEM_BYTES>>>(xh, wqt, bq, q, HID);
    gemm_tc<<<dim3(KVDIM / 128, M_ROWS / 256), 256, SMEM_BYTES>>>(xh, wkt, bk, k, KVDIM);
    gemm_tc<<<dim3(KVDIM / 128, M_ROWS / 256), 256, SMEM_BYTES>>>(xh, wvt, bv, v, KVDIM);

    // Attention (writes fp16 A operand for O-projection)
    attn_kernel<<<M_ROWS, 256>>>(q, k, v, attnh);

    // Output projection
    gemm_tc<<<dim3(HID / 128, M_ROWS / 256), 256, SMEM_BYTES>>>(attnh, wot, bo, out, HID);
}

// round 15
// speedup vs baseline: 2.9543x; 1.0050x over previous
#include <cuda_runtime.h>
#include <cuda_fp16.h>
#include <math.h>
#include <stdint.h>

// ---------------------------------------------------------------------------
// B=4, S=4096, HID=2048, H=16, G=4, D=128, KV=512, M = B*S = 16384, K = 2048
// ---------------------------------------------------------------------------
#define M_ROWS 16384
#define KDIM   2048
#define HID    2048
#define KVDIM  512

// Scratch (__device__ globals: allocation-free rule)
__device__ __align__(128) __half g_qh[(size_t)M_ROWS * HID];
__device__ __align__(128) __half g_kh[(size_t)M_ROWS * KVDIM];
__device__ __align__(128) __half g_vh[(size_t)M_ROWS * KVDIM];
__device__ __align__(128) __half g_attnh[(size_t)M_ROWS * HID];
__device__ __align__(128) __half g_xh[(size_t)M_ROWS * HID];
__device__ __align__(128) __half g_wqt[(size_t)HID * KDIM];
__device__ __align__(128) __half g_wkt[(size_t)KVDIM * KDIM];
__device__ __align__(128) __half g_wvt[(size_t)KVDIM * KDIM];
__device__ __align__(128) __half g_wot[(size_t)HID * KDIM];

// ---------------------------------------------------------------------------
// PTX helpers (base sm_103 ISA only)
// ---------------------------------------------------------------------------
__device__ __forceinline__ uint32_t smem_u32(const void* p) {
    uint32_t a;
    asm("{ .reg .u64 t; cvta.to.shared.u64 t, %1; cvt.u32.u64 %0, t; }" : "=r"(a) : "l"(p));
    return a;
}
__device__ __forceinline__ void cp_async16(uint32_t saddr, const void* gmem) {
    asm volatile("cp.async.cg.shared.global [%0], [%1], 16;\n" :: "r"(saddr), "l"(gmem));
}
__device__ __forceinline__ void cp_commit() { asm volatile("cp.async.commit_group;\n"); }
template <int N>
__device__ __forceinline__ void cp_wait() { asm volatile("cp.async.wait_group %0;\n" :: "n"(N)); }

__device__ __forceinline__ void ldsm4(uint32_t r[4], uint32_t addr) {
    asm volatile("ldmatrix.sync.aligned.m8n8.x4.shared.b16 {%0,%1,%2,%3}, [%4];"
                 : "=r"(r[0]), "=r"(r[1]), "=r"(r[2]), "=r"(r[3]) : "r"(addr));
}
// fp16 MMA, fp32 accumulate: m16n8k16
__device__ __forceinline__ void mma_f16(float c[4],
                                        const uint32_t a[4], uint32_t b0, uint32_t b1) {
    asm volatile(
        "mma.sync.aligned.m16n8k16.row.col.f32.f16.f16.f32 "
        "{%0,%1,%2,%3}, {%4,%5,%6,%7}, {%8,%9}, {%0,%1,%2,%3};\n"
        : "+f"(c[0]), "+f"(c[1]), "+f"(c[2]), "+f"(c[3])
        : "r"(a[0]), "r"(a[1]), "r"(a[2]), "r"(a[3]), "r"(b0), "r"(b1));
}

// ---------------------------------------------------------------------------
// GEMM: C[M,N] = A[M,K] @ Bt[N,K]^T + bias   (A,Bt fp16; C fp32 or fp16)
// CTA tile 256(M) x 128(N), BK=64 halves (128 B/row). 256 threads = 8 warps
// (4x2), warp tile 64x64. Per k16 step: 8 ldsm4 -> 32 m16n8k16 MMAs.
// 4-stage cp.async ring, XOR-swizzled smem. (Proven R13 structure.)
// ---------------------------------------------------------------------------
#define NSTAGE 4
#define KT_CNT 32                       // K / 64
#define STG_A  32768                    // 256 rows * 128 B
#define STG_B  16384                    // 128 rows * 128 B
#define SM_B_OFF (NSTAGE * STG_A)
#define SMEM_BYTES (NSTAGE * (STG_A + STG_B))   // 196608

template <typename OutT>
__global__ void __launch_bounds__(256, 1)
gemm_tc(const __half* __restrict__ A, const __half* __restrict__ Bt,
        const float* __restrict__ bias, OutT* __restrict__ C, int N) {
    extern __shared__ char smem[];
    const uint32_t sb = smem_u32(smem);
    const int tid = threadIdx.x, warp = tid >> 5, lane = tid & 31;
    const int wm = warp >> 1, wn = warp & 1;       // 4(m) x 2(n) warp grid
    const int bm = blockIdx.y * 256;
    const int bn = blockIdx.x * 128;

    // ---- per-lane ldmatrix address bases (swizzle folded; bits disjoint) ----
    uint32_t aBase[4], aXk, bBase[4], bXk[4];
    {
        const int f = lane >> 3;
        const int rinA = ((f & 1) << 3) | (lane & 7);
        const int cfA = f >> 1;
        const int rmA = rinA & 7;
        aXk = (uint32_t)((rmA & 6) << 4);
#pragma unroll
        for (int mi = 0; mi < 4; mi++) {
            const int row = wm * 64 + mi * 16 + rinA;
            aBase[mi] = (uint32_t)(row * 128 + ((cfA ^ (rmA & 1)) << 4));
        }
        const int rinB = ((f >> 1) << 3) | (lane & 7);
        const int cfB = f & 1;
#pragma unroll
        for (int p = 0; p < 4; p++) {
            const int nrow = wn * 64 + p * 16 + rinB;
            const int rm = nrow & 7;
            bBase[p] = (uint32_t)(nrow * 128 + ((cfB ^ (rm & 1)) << 4));
            bXk[p]   = (uint32_t)((rm & 6) << 4);
        }
    }

    float acc[4][8][4];
#pragma unroll
    for (int i = 0; i < 4; i++)
#pragma unroll
        for (int j = 0; j < 8; j++)
#pragma unroll
            for (int c = 0; c < 4; c++) acc[i][j][c] = 0.f;

    // gmem->smem: 16B chunks (=8 halves), swizzled chunk = c ^ (row&7)
    auto load_stage = [&](int kt, int buf) {
#pragma unroll
        for (int i = 0; i < 8; i++) {
            const int idx = tid + i * 256;
            const int row = idx >> 3, c = idx & 7;
            const uint32_t sw = (uint32_t)(row * 128 + ((c ^ (row & 7)) << 4));
            cp_async16(sb + buf * STG_A + sw,
                       A + (size_t)(bm + row) * KDIM + kt * 64 + c * 8);
        }
#pragma unroll
        for (int i = 0; i < 4; i++) {
            const int idx = tid + i * 256;
            const int row = idx >> 3, c = idx & 7;
            const uint32_t sw = (uint32_t)(row * 128 + ((c ^ (row & 7)) << 4));
            cp_async16(sb + SM_B_OFF + buf * STG_B + sw,
                       Bt + (size_t)(bn + row) * KDIM + kt * 64 + c * 8);
        }
        cp_commit();
    };

#pragma unroll
    for (int s = 0; s < NSTAGE; s++) load_stage(s, s);

    for (int kt = 0; kt < KT_CNT; kt++) {
        if (kt < KT_CNT - 2)       cp_wait<2>();
        else if (kt == KT_CNT - 2) cp_wait<1>();
        else                       cp_wait<0>();
        __syncthreads();
        if (kt >= 1 && kt + 3 < KT_CNT) load_stage(kt + 3, (kt + 3) & 3);

        const int buf = kt & 3;
        const uint32_t aS = sb + buf * STG_A;
        const uint32_t bS = sb + SM_B_OFF + buf * STG_B;
#pragma unroll
        for (int ks = 0; ks < 4; ks++) {
            uint32_t a[4][4];
#pragma unroll
            for (int mi = 0; mi < 4; mi++)
                ldsm4(a[mi], aS + (aBase[mi] | ((32u * ks) ^ aXk)));
            uint32_t b[4][4];
#pragma unroll
            for (int p = 0; p < 4; p++)
                ldsm4(b[p], bS + (bBase[p] | ((32u * ks) ^ bXk[p])));
#pragma unroll
            for (int mi = 0; mi < 4; mi++)
#pragma unroll
                for (int p = 0; p < 4; p++) {
                    mma_f16(acc[mi][2 * p],     a[mi], b[p][0], b[p][1]);
                    mma_f16(acc[mi][2 * p + 1], a[mi], b[p][2], b[p][3]);
                }
        }
    }

    // epilogue: + bias
    const int g = lane >> 2, tig = lane & 3;
#pragma unroll
    for (int mi = 0; mi < 4; mi++) {
#pragma unroll
        for (int ni = 0; ni < 8; ni++) {
            const int row = bm + wm * 64 + mi * 16 + g;
            const int col = bn + wn * 64 + ni * 8 + tig * 2;
            const float bv0 = bias[col], bv1 = bias[col + 1];
            const float v00 = acc[mi][ni][0] + bv0, v01 = acc[mi][ni][1] + bv1;
            const float v10 = acc[mi][ni][2] + bv0, v11 = acc[mi][ni][3] + bv1;
            if constexpr (sizeof(OutT) == 4) {
                *(float2*)((float*)C + (size_t)row * N + col)       = make_float2(v00, v01);
                *(float2*)((float*)C + (size_t)(row + 8) * N + col) = make_float2(v10, v11);
            } else {
                *(__half2*)((__half*)C + (size_t)row * N + col)       = __floats2half2_rn(v00, v01);
                *(__half2*)((__half*)C + (size_t)(row + 8) * N + col) = __floats2half2_rn(v10, v11);
            }
        }
    }
}

// ---------------------------------------------------------------------------
// Weight transpose + fp16 conversion: Wt[n,k] = half(W[k,n]); W is [K,N] fp32
// ---------------------------------------------------------------------------
__global__ void __launch_bounds__(256)
transpose_h(const float* __restrict__ W, __half* __restrict__ Wt, int K, int N) {
    __shared__ float t[32][33];
    const int k0 = blockIdx.x * 32, n0 = blockIdx.y * 32;
    const int tx = threadIdx.x & 31, ty = threadIdx.x >> 5;   // ty 0..7
#pragma unroll
    for (int i = 0; i < 32; i += 8)
        t[ty + i][tx] = W[(size_t)(k0 + ty + i) * N + n0 + tx];
    __syncthreads();
#pragma unroll
    for (int i = 0; i < 32; i += 8)
        Wt[(size_t)(n0 + ty + i) * K + k0 + tx] = __float2half_rn(t[tx][ty + i]);
}

// fp32 -> fp16 elementwise (activations feeding GEMM A operands)
__global__ void __launch_bounds__(256)
f2h4(const float4* __restrict__ in, __half2* __restrict__ out, int n4) {
    for (int i = blockIdx.x * 256 + threadIdx.x; i < n4; i += gridDim.x * 256) {
        float4 v = in[i];
        out[2 * i]     = __floats2half2_rn(v.x, v.y);
        out[2 * i + 1] = __floats2half2_rn(v.z, v.w);
    }
}

// ---------------------------------------------------------------------------
// Attention over G=4 groups at same position (q,k,v fp16; compute fp32;
// writes fp16 A operand for the O-projection).
// ---------------------------------------------------------------------------
__global__ void __launch_bounds__(256)
attn_kernel(const __half* __restrict__ Q, const __half* __restrict__ Kp,
            const __half* __restrict__ Vp, __half* __restrict__ Out) {
    const int m = blockIdx.x;
    __shared__ float ks[512], vs[512];
    const int tid = threadIdx.x;
    const __half* kr = Kp + (size_t)m * KVDIM;
    const __half* vr = Vp + (size_t)m * KVDIM;
    for (int i = tid; i < 512; i += 256) {
        ks[i] = __half2float(kr[i]);
        vs[i] = __half2float(vr[i]);
    }
    __syncthreads();

    const int warp = tid >> 5, lane = tid & 31;
    const __half* qr   = Q   + (size_t)m * HID;
    __half*       orow = Out + (size_t)m * HID;

#pragma unroll
    for (int hh = 0; hh < 2; ++hh) {
        const int h = warp * 2 + hh;
        float qv[4];
#pragma unroll
        for (int j = 0; j < 4; j++) qv[j] = __half2float(qr[h * 128 + lane + 32 * j]);
        float s[4];
#pragma unroll
        for (int gi = 0; gi < 4; ++gi) {
            float p = 0.f;
#pragma unroll
            for (int j = 0; j < 4; j++) p += qv[j] * ks[gi * 128 + lane + 32 * j];
#pragma unroll
            for (int off = 16; off > 0; off >>= 1)
                p += __shfl_xor_sync(0xffffffffu, p, off);
            s[gi] = p * 0.088388347648318447f;   // 1/sqrt(128)
        }
        const float mx = fmaxf(fmaxf(s[0], s[1]), fmaxf(s[2], s[3]));
        float e0 = __expf(s[0] - mx), e1 = __expf(s[1] - mx);
        float e2 = __expf(s[2] - mx), e3 = __expf(s[3] - mx);
        const float inv = 1.f / (e0 + e1 + e2 + e3);
        e0 *= inv; e1 *= inv; e2 *= inv; e3 *= inv;
#pragma unroll
        for (int j = 0; j < 4; j++) {
            const int d = lane + 32 * j;
            const float o = e0 * vs[d] + e1 * vs[128 + d] +
                            e2 * vs[256 + d] + e3 * vs[384 + d];
            orow[h * 128 + d] = __float2half_rn(o);
        }
    }
}

// ---------------------------------------------------------------------------
// Launch: hidden_states, Wq, bq, Wk, bk, Wv, bv, Wo, bo
// ---------------------------------------------------------------------------
extern "C" void kernel_launch(void* const* d_in, const int* in_sizes, int n_in,
                              void* d_out, int out_size) {
    const float* x  = (const float*)d_in[0];
    const float* Wq = (const float*)d_in[1];
    const float* bq = (const float*)d_in[2];
    const float* Wk = (const float*)d_in[3];
    const float* bk = (const float*)d_in[4];
    const float* Wv = (const float*)d_in[5];
    const float* bv = (const float*)d_in[6];
    const float* Wo = (const float*)d_in[7];
    const float* bo = (const float*)d_in[8];
    float* out = (float*)d_out;

    __half *qh, *kh, *vh, *attnh, *xh, *wqt, *wkt, *wvt, *wot;
    cudaGetSymbolAddress((void**)&qh,    g_qh);
    cudaGetSymbolAddress((void**)&kh,    g_kh);
    cudaGetSymbolAddress((void**)&vh,    g_vh);
    cudaGetSymbolAddress((void**)&attnh, g_attnh);
    cudaGetSymbolAddress((void**)&xh,    g_xh);
    cudaGetSymbolAddress((void**)&wqt,   g_wqt);
    cudaGetSymbolAddress((void**)&wkt,   g_wkt);
    cudaGetSymbolAddress((void**)&wvt,   g_wvt);
    cudaGetSymbolAddress((void**)&wot,   g_wot);

    cudaFuncSetAttribute(gemm_tc<__half>, cudaFuncAttributeMaxDynamicSharedMemorySize, SMEM_BYTES);
    cudaFuncSetAttribute(gemm_tc<float>,  cudaFuncAttributeMaxDynamicSharedMemorySize, SMEM_BYTES);

    // Prep: transpose+convert weights, convert activations
    transpose_h<<<dim3(KDIM / 32, HID / 32),   256>>>(Wq, wqt, KDIM, HID);
    transpose_h<<<dim3(KDIM / 32, KVDIM / 32), 256>>>(Wk, wkt, KDIM, KVDIM);
    transpose_h<<<dim3(KDIM / 32, KVDIM / 32), 256>>>(Wv, wvt, KDIM, KVDIM);
    transpose_h<<<dim3(KDIM / 32, HID / 32),   256>>>(Wo, wot, KDIM, HID);
    f2h4<<<8192, 256>>>((const float4*)x, (__half2*)xh, (M_ROWS * HID) / 4);

    // Projections (fp16 tensor cores, m16n8k16, fp32 accumulate, fp16 out)
    gemm_tc<__half><<<dim3(HID / 128,   M_ROWS / 256), 256, SMEM_BYTES>>>(xh, wqt, bq, qh, HID);
    gemm_tc<__half><<<dim3(KVDIM / 128, M_ROWS / 256), 256, SMEM_BYTES>>>(xh, wkt, bk, kh, KVDIM);
    gemm_tc<__half><<<dim3(KVDIM / 128, M_ROWS / 256), 256, SMEM_BYTES>>>(xh, wvt, bv, vh, KVDIM);

    // Attention (fp16 in/out, fp32 compute)
    attn_kernel<<<M_ROWS, 256>>>(qh, kh, vh, attnh);

    // Output projection (fp32 out to d_out)
    gemm_tc<float><<<dim3(HID / 128, M_ROWS / 256), 256, SMEM_BYTES>>>(attnh, wot, bo, out, HID);
}

// round 16
// speedup vs baseline: 3.1594x; 1.0695x over previous
#include <cuda_runtime.h>
#include <cuda_fp16.h>
#include <math.h>
#include <stdint.h>

// ---------------------------------------------------------------------------
// B=4, S=4096, HID=2048, H=16, G=4, D=128, KV=512, M = B*S = 16384, K = 2048
// ---------------------------------------------------------------------------
#define M_ROWS 16384
#define KDIM   2048
#define HID    2048
#define KVDIM  512

// Scratch (__device__ globals: allocation-free rule)
__device__ __align__(128) __half g_qh[(size_t)M_ROWS * HID];
__device__ __align__(128) __half g_kh[(size_t)M_ROWS * KVDIM];
__device__ __align__(128) __half g_vh[(size_t)M_ROWS * KVDIM];
__device__ __align__(128) __half g_attnh[(size_t)M_ROWS * HID];
__device__ __align__(128) __half g_xh[(size_t)M_ROWS * HID];
__device__ __align__(128) __half g_wqt[(size_t)HID * KDIM];
__device__ __align__(128) __half g_wkt[(size_t)KVDIM * KDIM];
__device__ __align__(128) __half g_wvt[(size_t)KVDIM * KDIM];
__device__ __align__(128) __half g_wot[(size_t)HID * KDIM];

// ---------------------------------------------------------------------------
// PTX helpers (base sm_103 ISA only)
// ---------------------------------------------------------------------------
__device__ __forceinline__ uint32_t smem_u32(const void* p) {
    uint32_t a;
    asm("{ .reg .u64 t; cvta.to.shared.u64 t, %1; cvt.u32.u64 %0, t; }" : "=r"(a) : "l"(p));
    return a;
}
__device__ __forceinline__ void cp_async16(uint32_t saddr, const void* gmem) {
    asm volatile("cp.async.cg.shared.global [%0], [%1], 16;\n" :: "r"(saddr), "l"(gmem));
}
__device__ __forceinline__ void cp_commit() { asm volatile("cp.async.commit_group;\n"); }
template <int N>
__device__ __forceinline__ void cp_wait() { asm volatile("cp.async.wait_group %0;\n" :: "n"(N)); }

__device__ __forceinline__ void ldsm4(uint32_t r[4], uint32_t addr) {
    asm volatile("ldmatrix.sync.aligned.m8n8.x4.shared.b16 {%0,%1,%2,%3}, [%4];"
                 : "=r"(r[0]), "=r"(r[1]), "=r"(r[2]), "=r"(r[3]) : "r"(addr));
}
// fp16 MMA, fp32 accumulate: m16n8k16
__device__ __forceinline__ void mma_f16(float c[4],
                                        const uint32_t a[4], uint32_t b0, uint32_t b1) {
    asm volatile(
        "mma.sync.aligned.m16n8k16.row.col.f32.f16.f16.f32 "
        "{%0,%1,%2,%3}, {%4,%5,%6,%7}, {%8,%9}, {%0,%1,%2,%3};\n"
        : "+f"(c[0]), "+f"(c[1]), "+f"(c[2]), "+f"(c[3])
        : "r"(a[0]), "r"(a[1]), "r"(a[2]), "r"(a[3]), "r"(b0), "r"(b1));
}

// ---------------------------------------------------------------------------
// GEMM: C[M,N] = A[M,K] @ Bt[N,K]^T + bias   (A,Bt fp16; C fp32 or fp16)
// CTA tile 256(M) x 128(N), BK=64 halves (128 B/row). 256 threads = 8 warps
// (4x2), warp tile 64x64. 4-stage cp.async ring + REGISTER fragment
// double-buffer: LDSMs for step i+1 issue before MMAs of step i, across both
// ks and kt boundaries, so the tensor pipe never waits on shared-mem latency.
// ---------------------------------------------------------------------------
#define NSTAGE 4
#define KT_CNT 32                       // K / 64
#define STG_A  32768                    // 256 rows * 128 B
#define STG_B  16384                    // 128 rows * 128 B
#define SM_B_OFF (NSTAGE * STG_A)
#define SMEM_BYTES (NSTAGE * (STG_A + STG_B))   // 196608

template <typename OutT>
__global__ void __launch_bounds__(256, 1)
gemm_tc(const __half* __restrict__ A, const __half* __restrict__ Bt,
        const float* __restrict__ bias, OutT* __restrict__ C, int N) {
    extern __shared__ char smem[];
    const uint32_t sb = smem_u32(smem);
    const int tid = threadIdx.x, warp = tid >> 5, lane = tid & 31;
    const int wm = warp >> 1, wn = warp & 1;       // 4(m) x 2(n) warp grid
    const int bm = blockIdx.y * 256;
    const int bn = blockIdx.x * 128;

    // ---- per-lane ldmatrix address bases (swizzle folded; bits disjoint) ----
    uint32_t aBase[4], aXk, bBase[4], bXk[4];
    {
        const int f = lane >> 3;
        const int rinA = ((f & 1) << 3) | (lane & 7);
        const int cfA = f >> 1;
        const int rmA = rinA & 7;
        aXk = (uint32_t)((rmA & 6) << 4);
#pragma unroll
        for (int mi = 0; mi < 4; mi++) {
            const int row = wm * 64 + mi * 16 + rinA;
            aBase[mi] = (uint32_t)(row * 128 + ((cfA ^ (rmA & 1)) << 4));
        }
        const int rinB = ((f >> 1) << 3) | (lane & 7);
        const int cfB = f & 1;
#pragma unroll
        for (int p = 0; p < 4; p++) {
            const int nrow = wn * 64 + p * 16 + rinB;
            const int rm = nrow & 7;
            bBase[p] = (uint32_t)(nrow * 128 + ((cfB ^ (rm & 1)) << 4));
            bXk[p]   = (uint32_t)((rm & 6) << 4);
        }
    }

    float acc[4][8][4];
#pragma unroll
    for (int i = 0; i < 4; i++)
#pragma unroll
        for (int j = 0; j < 8; j++)
#pragma unroll
            for (int c = 0; c < 4; c++) acc[i][j][c] = 0.f;

    // gmem->smem: 16B chunks (=8 halves), swizzled chunk = c ^ (row&7)
    auto load_stage = [&](int kt, int buf) {
#pragma unroll
        for (int i = 0; i < 8; i++) {
            const int idx = tid + i * 256;
            const int row = idx >> 3, c = idx & 7;
            const uint32_t sw = (uint32_t)(row * 128 + ((c ^ (row & 7)) << 4));
            cp_async16(sb + buf * STG_A + sw,
                       A + (size_t)(bm + row) * KDIM + kt * 64 + c * 8);
        }
#pragma unroll
        for (int i = 0; i < 4; i++) {
            const int idx = tid + i * 256;
            const int row = idx >> 3, c = idx & 7;
            const uint32_t sw = (uint32_t)(row * 128 + ((c ^ (row & 7)) << 4));
            cp_async16(sb + SM_B_OFF + buf * STG_B + sw,
                       Bt + (size_t)(bn + row) * KDIM + kt * 64 + c * 8);
        }
        cp_commit();
    };

    // register fragment double buffer (pb = ks & 1)
    uint32_t afr[2][4][4], bfr[2][4][4];
    auto load_frags = [&](int kt, int ks, int wb) {
        const uint32_t aS = sb + (kt & 3) * STG_A;
        const uint32_t bS = sb + SM_B_OFF + (kt & 3) * STG_B;
#pragma unroll
        for (int mi = 0; mi < 4; mi++)
            ldsm4(afr[wb][mi], aS + (aBase[mi] | ((32u * ks) ^ aXk)));
#pragma unroll
        for (int p = 0; p < 4; p++)
            ldsm4(bfr[wb][p], bS + (bBase[p] | ((32u * ks) ^ bXk[p])));
    };

#pragma unroll
    for (int s = 0; s < NSTAGE; s++) load_stage(s, s);
    cp_wait<2>();            // stages 0,1 complete
    __syncthreads();         // ...and visible to all warps
    load_frags(0, 0, 0);

    for (int kt = 0; kt < KT_CNT; kt++) {
        if (kt >= 1 && kt + 3 < KT_CNT) load_stage(kt + 3, (kt + 3) & 3);
#pragma unroll
        for (int ks = 0; ks < 4; ks++) {
            const int cb = ks & 1, nb = cb ^ 1;
            // prefetch next step's fragments BEFORE consuming current ones
            if (ks < 3)               load_frags(kt, ks + 1, nb);
            else if (kt + 1 < KT_CNT) load_frags(kt + 1, 0, nb);   // next ring buffer (complete per cp_wait)
#pragma unroll
            for (int mi = 0; mi < 4; mi++)
#pragma unroll
                for (int p = 0; p < 4; p++) {
                    mma_f16(acc[mi][2 * p],     afr[cb][mi], bfr[cb][p][0], bfr[cb][p][1]);
                    mma_f16(acc[mi][2 * p + 1], afr[cb][mi], bfr[cb][p][2], bfr[cb][p][3]);
                }
        }
        if (kt + 1 < KT_CNT) {
            // after this wait, stages <= kt+2 are complete (needed by next
            // iter's cross-kt prefetch); near the tail, drain fully.
            if (kt < KT_CNT - 3) cp_wait<1>();
            else                 cp_wait<0>();
            __syncthreads();
        }
    }

    // epilogue: + bias
    const int g = lane >> 2, tig = lane & 3;
#pragma unroll
    for (int mi = 0; mi < 4; mi++) {
#pragma unroll
        for (int ni = 0; ni < 8; ni++) {
            const int row = bm + wm * 64 + mi * 16 + g;
            const int col = bn + wn * 64 + ni * 8 + tig * 2;
            const float bv0 = bias[col], bv1 = bias[col + 1];
            const float v00 = acc[mi][ni][0] + bv0, v01 = acc[mi][ni][1] + bv1;
            const float v10 = acc[mi][ni][2] + bv0, v11 = acc[mi][ni][3] + bv1;
            if constexpr (sizeof(OutT) == 4) {
                *(float2*)((float*)C + (size_t)row * N + col)       = make_float2(v00, v01);
                *(float2*)((float*)C + (size_t)(row + 8) * N + col) = make_float2(v10, v11);
            } else {
                *(__half2*)((__half*)C + (size_t)row * N + col)       = __floats2half2_rn(v00, v01);
                *(__half2*)((__half*)C + (size_t)(row + 8) * N + col) = __floats2half2_rn(v10, v11);
            }
        }
    }
}

// ---------------------------------------------------------------------------
// Weight transpose + fp16 conversion: Wt[n,k] = half(W[k,n]); W is [K,N] fp32
// ---------------------------------------------------------------------------
__global__ void __launch_bounds__(256)
transpose_h(const float* __restrict__ W, __half* __restrict__ Wt, int K, int N) {
    __shared__ float t[32][33];
    const int k0 = blockIdx.x * 32, n0 = blockIdx.y * 32;
    const int tx = threadIdx.x & 31, ty = threadIdx.x >> 5;   // ty 0..7
#pragma unroll
    for (int i = 0; i < 32; i += 8)
        t[ty + i][tx] = W[(size_t)(k0 + ty + i) * N + n0 + tx];
    __syncthreads();
#pragma unroll
    for (int i = 0; i < 32; i += 8)
        Wt[(size_t)(n0 + ty + i) * K + k0 + tx] = __float2half_rn(t[tx][ty + i]);
}

// fp32 -> fp16 elementwise (activations feeding GEMM A operands)
__global__ void __launch_bounds__(256)
f2h4(const float4* __restrict__ in, __half2* __restrict__ out, int n4) {
    for (int i = blockIdx.x * 256 + threadIdx.x; i < n4; i += gridDim.x * 256) {
        float4 v = in[i];
        out[2 * i]     = __floats2half2_rn(v.x, v.y);
        out[2 * i + 1] = __floats2half2_rn(v.z, v.w);
    }
}

// ---------------------------------------------------------------------------
// Attention over G=4 groups at same position (q,k,v fp16; compute fp32;
// writes fp16 A operand for the O-projection).
// ---------------------------------------------------------------------------
__global__ void __launch_bounds__(256)
attn_kernel(const __half* __restrict__ Q, const __half* __restrict__ Kp,
            const __half* __restrict__ Vp, __half* __restrict__ Out) {
    const int m = blockIdx.x;
    __shared__ float ks[512], vs[512];
    const int tid = threadIdx.x;
    const __half* kr = Kp + (size_t)m * KVDIM;
    const __half* vr = Vp + (size_t)m * KVDIM;
    for (int i = tid; i < 512; i += 256) {
        ks[i] = __half2float(kr[i]);
        vs[i] = __half2float(vr[i]);
    }
    __syncthreads();

    const int warp = tid >> 5, lane = tid & 31;
    const __half* qr   = Q   + (size_t)m * HID;
    __half*       orow = Out + (size_t)m * HID;

#pragma unroll
    for (int hh = 0; hh < 2; ++hh) {
        const int h = warp * 2 + hh;
        float qv[4];
#pragma unroll
        for (int j = 0; j < 4; j++) qv[j] = __half2float(qr[h * 128 + lane + 32 * j]);
        float s[4];
#pragma unroll
        for (int gi = 0; gi < 4; ++gi) {
            float p = 0.f;
#pragma unroll
            for (int j = 0; j < 4; j++) p += qv[j] * ks[gi * 128 + lane + 32 * j];
#pragma unroll
            for (int off = 16; off > 0; off >>= 1)
                p += __shfl_xor_sync(0xffffffffu, p, off);
            s[gi] = p * 0.088388347648318447f;   // 1/sqrt(128)
        }
        const float mx = fmaxf(fmaxf(s[0], s[1]), fmaxf(s[2], s[3]));
        float e0 = __expf(s[0] - mx), e1 = __expf(s[1] - mx);
        float e2 = __expf(s[2] - mx), e3 = __expf(s[3] - mx);
        const float inv = 1.f / (e0 + e1 + e2 + e3);
        e0 *= inv; e1 *= inv; e2 *= inv; e3 *= inv;
#pragma unroll
        for (int j = 0; j < 4; j++) {
            const int d = lane + 32 * j;
            const float o = e0 * vs[d] + e1 * vs[128 + d] +
                            e2 * vs[256 + d] + e3 * vs[384 + d];
            orow[h * 128 + d] = __float2half_rn(o);
        }
    }
}

// ---------------------------------------------------------------------------
// Launch: hidden_states, Wq, bq, Wk, bk, Wv, bv, Wo, bo
// ---------------------------------------------------------------------------
extern "C" void kernel_launch(void* const* d_in, const int* in_sizes, int n_in,
                              void* d_out, int out_size) {
    const float* x  = (const float*)d_in[0];
    const float* Wq = (const float*)d_in[1];
    const float* bq = (const float*)d_in[2];
    const float* Wk = (const float*)d_in[3];
    const float* bk = (const float*)d_in[4];
    const float* Wv = (const float*)d_in[5];
    const float* bv = (const float*)d_in[6];
    const float* Wo = (const float*)d_in[7];
    const float* bo = (const float*)d_in[8];
    float* out = (float*)d_out;

    __half *qh, *kh, *vh, *attnh, *xh, *wqt, *wkt, *wvt, *wot;
    cudaGetSymbolAddress((void**)&qh,    g_qh);
    cudaGetSymbolAddress((void**)&kh,    g_kh);
    cudaGetSymbolAddress((void**)&vh,    g_vh);
    cudaGetSymbolAddress((void**)&attnh, g_attnh);
    cudaGetSymbolAddress((void**)&xh,    g_xh);
    cudaGetSymbolAddress((void**)&wqt,   g_wqt);
    cudaGetSymbolAddress((void**)&wkt,   g_wkt);
    cudaGetSymbolAddress((void**)&wvt,   g_wvt);
    cudaGetSymbolAddress((void**)&wot,   g_wot);

    cudaFuncSetAttribute(gemm_tc<__half>, cudaFuncAttributeMaxDynamicSharedMemorySize, SMEM_BYTES);
    cudaFuncSetAttribute(gemm_tc<float>,  cudaFuncAttributeMaxDynamicSharedMemorySize, SMEM_BYTES);

    // Prep: transpose+convert weights, convert activations
    transpose_h<<<dim3(KDIM / 32, HID / 32),   256>>>(Wq, wqt, KDIM, HID);
    transpose_h<<<dim3(KDIM / 32, KVDIM / 32), 256>>>(Wk, wkt, KDIM, KVDIM);
    transpose_h<<<dim3(KDIM / 32, KVDIM / 32), 256>>>(Wv, wvt, KDIM, KVDIM);
    transpose_h<<<dim3(KDIM / 32, HID / 32),   256>>>(Wo, wot, KDIM, HID);
    f2h4<<<8192, 256>>>((const float4*)x, (__half2*)xh, (M_ROWS * HID) / 4);

    // Projections (fp16 tensor cores, m16n8k16, fp32 accumulate, fp16 out)
    gemm_tc<__half><<<dim3(HID / 128,   M_ROWS / 256), 256, SMEM_BYTES>>>(xh, wqt, bq, qh, HID);
    gemm_tc<__half><<<dim3(KVDIM / 128, M_ROWS / 256), 256, SMEM_BYTES>>>(xh, wkt, bk, kh, KVDIM);
    gemm_tc<__half><<<dim3(KVDIM / 128, M_ROWS / 256), 256, SMEM_BYTES>>>(xh, wvt, bv, vh, KVDIM);

    // Attention (fp16 in/out, fp32 compute)
    attn_kernel<<<M_ROWS, 256>>>(qh, kh, vh, attnh);

    // Output projection (fp32 out to d_out)
    gemm_tc<float><<<dim3(HID / 128, M_ROWS / 256), 256, SMEM_BYTES>>>(attnh, wot, bo, out, HID);
}